// round 16
// baseline (speedup 1.0000x reference)
#include <cuda_runtime.h>
#include <cuda_bf16.h>
#include <cstdint>

// ApplyKmeans: tokens[n] = argmin_k ( Cnorm[k] - 2 * dot(x[n], C[:,k]) )
// Output: float32 token values. Inputs bound by element count.
//
// R16:
//  * X->bf16 conversion fused into the GEMM A-path (LDG fp32 -> cvt -> STS),
//    standalone convert kernel removed. CTA tile 64(M) x 160(N) to keep regs
//    <=128 at 2 CTAs/SM (acc 80 + staging 8 + frags 18).
//  * rescore v2: no smem staging, float4 lane-strided dots with 4 partial
//    sums (MLP up, FMA chain broken), higher occupancy.
// Margin-24 bf16 candidate logic + exact fp32 rescore unchanged (rel_err 0.0
// across R13/R15).

static constexpr int ND    = 1024;
static constexpr int NK    = 300;
static constexpr int NKP   = 320;        // padded clusters
static constexpr int DSTR  = 304;        // dist row stride
static constexpr long long NROWS = 131072;

__device__ __align__(256) float          g_Ct [(size_t)NKP * ND];   // fp32 Ct[k][d]
__device__ __align__(256) __nv_bfloat16  g_Ctb[(size_t)NKP * ND];   // bf16 Ct[k][d]
__device__ __align__(256) float          g_dist[(size_t)NROWS * DSTR];

// ---------------------------------------------------------------- helpers
__device__ __forceinline__ uint32_t smem_u32(const void* p) {
    uint32_t a;
    asm("{ .reg .u64 t; cvta.to.shared.u64 t, %1; cvt.u32.u64 %0, t; }"
        : "=r"(a) : "l"(p));
    return a;
}
__device__ __forceinline__ void cp16(uint32_t dst, const void* src) {
    asm volatile("cp.async.cg.shared.global [%0], [%1], 16;"
                 :: "r"(dst), "l"(src) : "memory");
}
#define CP_COMMIT()  asm volatile("cp.async.commit_group;" ::: "memory")
#define CP_WAIT(n)   asm volatile("cp.async.wait_group %0;" :: "n"(n) : "memory")
#define SMEM_SWZ(o)  ((o) ^ (((o) >> 3) & 0x70))

__device__ __forceinline__ void mma_bf16(float* d, const uint32_t* a, const uint32_t* b) {
    asm volatile(
        "mma.sync.aligned.m16n8k16.row.col.f32.bf16.bf16.f32 "
        "{%0,%1,%2,%3}, {%4,%5,%6,%7}, {%8,%9}, {%0,%1,%2,%3};"
        : "+f"(d[0]), "+f"(d[1]), "+f"(d[2]), "+f"(d[3])
        : "r"(a[0]), "r"(a[1]), "r"(a[2]), "r"(a[3]), "r"(b[0]), "r"(b[1]));
}
__device__ __forceinline__ uint32_t pack_bf16(float a, float b) {
    __nv_bfloat162 h = __floats2bfloat162_rn(a, b);
    return *reinterpret_cast<uint32_t*>(&h);
}

// ---------------------------------------------------------------- kernel 1
__global__ void transpose_C_kernel(const float* __restrict__ C) {
    int i = blockIdx.x * 256 + threadIdx.x;
    if (i >= NKP * ND) return;
    int k = i >> 10;
    int d = i & (ND - 1);
    float v = (k < NK) ? C[d * NK + k] : 0.0f;
    g_Ct[i]  = v;
    g_Ctb[i] = __float2bfloat16_rn(v);
}

// ---------------------------------------------------------------- kernel 2
// bf16 mma.sync GEMM, CTA 64(M) x 160(N), 8 warps (2m x 4n), warp 32x40.
// A: LDG fp32 X -> cvt bf16 regs -> STS (fused conversion). B: cp.async.
// K chunks of 64 bf16 (one SW128 128B row), double-buffered, 2 CTAs/SM.
#define CH        16                     // 1024 / 64
#define A_BYTES   (64 * 128)             // 8 KB per buffer
#define B_BYTES   (160 * 128)            // 20 KB per buffer
#define SMEM_TOT  (2 * (A_BYTES + B_BYTES))   // 56 KB

__global__ __launch_bounds__(256, 2)
void dist_bf16_kernel(const float* __restrict__ X, const float* __restrict__ Cn)
{
    extern __shared__ char smem[];
    const uint32_t sb = smem_u32(smem);
    // layout: [A0][A1][B0][B1]
    const uint32_t sA0 = sb;
    const uint32_t sB0 = sb + 2 * A_BYTES;

    const int tid  = threadIdx.x;
    const int warp = tid >> 5;
    const int lane = tid & 31;
    const int g    = lane >> 2;          // 0..7
    const int t    = lane & 3;           // 0..3
    const int m0   = (warp >> 2) * 32;   // 0 or 32
    const int n0w  = (warp & 3) * 40;    // 0,40,80,120

    const size_t row0 = (size_t)blockIdx.x * 64;
    const int    kc0  = blockIdx.y * 160;

    const float*         xb = X     + row0 * ND;
    const __nv_bfloat16* cb = g_Ctb + (size_t)kc0 * ND;

    float acc[2][5][4];
    #pragma unroll
    for (int i = 0; i < 2; ++i)
        #pragma unroll
        for (int j = 0; j < 5; ++j)
            #pragma unroll
            for (int r = 0; r < 4; ++r) acc[i][j][r] = 0.0f;

    // A load map: 4 threads/row, 16 f32 each.
    const int a_row = tid >> 2;              // 0..63
    const int a_h   = (tid & 3) * 16;        // f32 col base 0,16,32,48

    uint32_t stA[8];                         // staged bf16 pairs (16 vals)

    auto ldgA = [&](int c) {                 // fp32 LDG + convert to bf16 regs
        const int d0 = c * 64;
        #pragma unroll
        for (int q = 0; q < 4; ++q) {
            float4 f = *(const float4*)(xb + (size_t)a_row * ND + d0 + a_h + q * 4);
            stA[q * 2 + 0] = pack_bf16(f.x, f.y);
            stA[q * 2 + 1] = pack_bf16(f.z, f.w);
        }
    };
    auto stsA = [&](int buf) {               // 32 bytes, swizzled
        const uint32_t base = sA0 + buf * A_BYTES;
        const uint32_t bo = (uint32_t)(a_row * 128 + a_h * 2);
        *(uint4*)(smem + (base - sb) + SMEM_SWZ(bo)) =
            make_uint4(stA[0], stA[1], stA[2], stA[3]);
        *(uint4*)(smem + (base - sb) + SMEM_SWZ(bo + 16)) =
            make_uint4(stA[4], stA[5], stA[6], stA[7]);
    };
    auto cpB = [&](int c, int buf) {
        const int d0 = c * 64;
        const uint32_t b_base = sB0 + buf * B_BYTES;
        #pragma unroll
        for (int q = 0; q < 5; ++q) {        // 160 rows x 8 cp16 = 1280 / 256
            int idx = tid + q * 256;
            int r = idx >> 3, bo = (idx & 7) * 16;
            cp16(b_base + SMEM_SWZ((uint32_t)(r * 128 + bo)),
                 cb + (size_t)r * ND + d0 + (bo >> 1));
        }
        CP_COMMIT();
    };

    // ---- prologue ----
    ldgA(0); stsA(0);
    cpB(0, 0);
    ldgA(1);                 // A1 staged in regs
    cpB(1, 1);

    for (int it = 0; it < CH; ++it) {
        const int cur = it & 1;
        if (it + 1 < CH) { CP_WAIT(1); } else { CP_WAIT(0); }   // B_it arrived
        __syncthreads();                                        // + A_it STS visible

        const char* As = smem + (cur * A_BYTES);
        const char* Bs = smem + (2 * A_BYTES + cur * B_BYTES);

        #pragma unroll
        for (int k16 = 0; k16 < 4; ++k16) {
            const int kb = k16 * 16;
            uint32_t af[2][4];
            #pragma unroll
            for (int i = 0; i < 2; ++i) {
                const int mr = m0 + 16 * i + g;
                af[i][0] = *(const uint32_t*)(As + SMEM_SWZ((uint32_t)(mr * 128 + (kb + 2*t) * 2)));
                af[i][1] = *(const uint32_t*)(As + SMEM_SWZ((uint32_t)((mr + 8) * 128 + (kb + 2*t) * 2)));
                af[i][2] = *(const uint32_t*)(As + SMEM_SWZ((uint32_t)(mr * 128 + (kb + 2*t + 8) * 2)));
                af[i][3] = *(const uint32_t*)(As + SMEM_SWZ((uint32_t)((mr + 8) * 128 + (kb + 2*t + 8) * 2)));
            }
            uint32_t bfr[5][2];
            #pragma unroll
            for (int j = 0; j < 5; ++j) {
                const int nr = n0w + 8 * j + g;
                bfr[j][0] = *(const uint32_t*)(Bs + SMEM_SWZ((uint32_t)(nr * 128 + (kb + 2*t) * 2)));
                bfr[j][1] = *(const uint32_t*)(Bs + SMEM_SWZ((uint32_t)(nr * 128 + (kb + 2*t + 8) * 2)));
            }
            #pragma unroll
            for (int i = 0; i < 2; ++i)
                #pragma unroll
                for (int j = 0; j < 5; ++j)
                    mma_bf16(acc[i][j], af[i], bfr[j]);
        }

        __syncthreads();                     // all warps done with buf cur
        if (it + 1 < CH) stsA(cur ^ 1);      // stage A(it+1) regs -> other buf
        if (it + 2 < CH) { ldgA(it + 2); cpB(it + 2, cur); }
    }

    // ---- epilogue: dist = Cn[k] - 2*dot ----
    #pragma unroll
    for (int j = 0; j < 5; ++j) {
        const int k0 = kc0 + n0w + 8 * j + 2 * t;
        const float cn0 = (k0     < NK) ? Cn[k0]     : 0.0f;
        const float cn1 = (k0 + 1 < NK) ? Cn[k0 + 1] : 0.0f;
        #pragma unroll
        for (int i = 0; i < 2; ++i) {
            const size_t r = row0 + m0 + 16 * i + g;
            if (k0 < NK) {
                g_dist[r * DSTR + k0]       = cn0 - 2.0f * acc[i][j][0];
                g_dist[(r + 8) * DSTR + k0] = cn0 - 2.0f * acc[i][j][2];
            }
            if (k0 + 1 < NK) {
                g_dist[r * DSTR + k0 + 1]       = cn1 - 2.0f * acc[i][j][1];
                g_dist[(r + 8) * DSTR + k0 + 1] = cn1 - 2.0f * acc[i][j][3];
            }
        }
    }
}

// ---------------------------------------------------------------- kernel 3
// Rescore v2: one warp per row, no smem. Approx min over 300, margin
// candidates, exact fp32 re-evaluation with float4 strided dots.
__global__ __launch_bounds__(256)
void rescore_kernel(const float* __restrict__ X,
                    const float* __restrict__ Cn,
                    float* __restrict__ out)
{
    const int tid  = threadIdx.x;
    const int warp = tid >> 5;
    const int lane = tid & 31;
    const size_t r = (size_t)blockIdx.x * 8 + warp;
    const float INF = __int_as_float(0x7f800000);
    const float MARGIN = 24.0f;          // bf16 chain bound ~12, 2x safety

    const float* drow = g_dist + r * DSTR;

    float vals[10];
    float minv = INF; int mink = 0;
    #pragma unroll
    for (int c = 0; c < 10; ++c) {
        int k = c * 32 + lane;
        float v = (k < NK) ? drow[k] : INF;
        vals[c] = v;
        if (v < minv) { minv = v; mink = k; }
    }
    #pragma unroll
    for (int off = 16; off; off >>= 1) {
        float ov = __shfl_xor_sync(0xffffffffu, minv, off);
        int   ok = __shfl_xor_sync(0xffffffffu, mink, off);
        if (ov < minv || (ov == minv && ok < mink)) { minv = ov; mink = ok; }
    }
    const float thr = minv + MARGIN;

    const float4* xr = (const float4*)(X + r * ND);

    float bestv = INF; int bestk = 0;
    #pragma unroll
    for (int c = 0; c < 10; ++c) {
        unsigned m = __ballot_sync(0xffffffffu, vals[c] < thr);
        while (m) {
            int b = __ffs(m) - 1; m &= m - 1;
            int k = c * 32 + b;                       // ascending k overall
            const float4* cr = (const float4*)(g_Ct + (size_t)k * ND);
            float s0 = 0.f, s1 = 0.f, s2 = 0.f, s3 = 0.f;
            #pragma unroll
            for (int i = 0; i < 8; ++i) {             // 256 float4 / 32 lanes
                float4 xv = __ldg(&xr[lane + i * 32]);
                float4 cv = __ldg(&cr[lane + i * 32]);
                s0 = fmaf(xv.x, cv.x, s0);
                s1 = fmaf(xv.y, cv.y, s1);
                s2 = fmaf(xv.z, cv.z, s2);
                s3 = fmaf(xv.w, cv.w, s3);
            }
            float a = (s0 + s1) + (s2 + s3);
            #pragma unroll
            for (int off = 16; off; off >>= 1)
                a += __shfl_xor_sync(0xffffffffu, a, off);
            float de = Cn[k] - 2.0f * a;              // exact fp32 distance
            if (de < bestv) { bestv = de; bestk = k; }  // strict <: first-min
        }
    }
    if (lane == 0) out[r] = (float)bestk;
}

// ---------------------------------------------------------------- launch
extern "C" void kernel_launch(void* const* d_in, const int* in_sizes, int n_in,
                              void* d_out, int out_size) {
    // Bind inputs BY ELEMENT COUNT (x = largest; C = 307200; Cnorm = 300).
    const float* x  = nullptr;
    const float* C  = nullptr;
    const float* Cn = nullptr;
    long long x_elems = 0;
    for (int i = 0; i < n_in; ++i) {
        const long long sz = in_sizes[i];
        if (sz > x_elems) { x = (const float*)d_in[i]; x_elems = sz; }
    }
    for (int i = 0; i < n_in; ++i) {
        const long long sz = in_sizes[i];
        if (sz == (long long)307200) C  = (const float*)d_in[i];
        else if (sz == (long long)300) Cn = (const float*)d_in[i];
    }
    if (!C || !Cn) {   // fallback, should not trigger
        x  = (const float*)d_in[0]; x_elems = in_sizes[0];
        C  = (const float*)d_in[1];
        Cn = (const float*)d_in[2];
    }

    float* out = (float*)d_out;                 // [131072] float32 token values
    const int n_rows = (int)(x_elems / ND);     // 131072

    transpose_C_kernel<<<(NKP * ND + 255) / 256, 256>>>(C);

    cudaFuncSetAttribute(dist_bf16_kernel,
                         cudaFuncAttributeMaxDynamicSharedMemorySize, SMEM_TOT);
    dim3 gridB(n_rows / 64, NKP / 160);         // (2048, 2)
    dist_bf16_kernel<<<gridB, 256, SMEM_TOT>>>(x, Cn);

    rescore_kernel<<<n_rows / 8, 256>>>(x, Cn, out);
}

// round 17
// speedup vs baseline: 1.1655x; 1.1655x over previous
#include <cuda_runtime.h>
#include <cuda_bf16.h>
#include <cstdint>

// ApplyKmeans: tokens[n] = argmin_k ( Cnorm[k] - 2 * dot(x[n], C[:,k]) )
// Output: float32 token values. Inputs bound by element count.
//
// R17: R16 regression disentangled — the fused-conversion M=64 GEMM was the
// culprit. GEMM reverted to the R15-proven shape (128x160, cp.async A+B from
// pre-converted g_Xb, 2 CTAs/SM). Kept ONLY rescore v2 (no smem staging,
// float4 dots with 4 partial sums). Margin-24 + exact fp32 rescore unchanged.

static constexpr int ND    = 1024;
static constexpr int NK    = 300;
static constexpr int NKP   = 320;        // padded clusters
static constexpr int DSTR  = 304;        // dist row stride
static constexpr long long NROWS = 131072;

__device__ __align__(256) float          g_Ct [(size_t)NKP * ND];   // fp32 Ct[k][d]
__device__ __align__(256) __nv_bfloat16  g_Ctb[(size_t)NKP * ND];   // bf16 Ct[k][d]
__device__ __align__(256) __nv_bfloat16  g_Xb [(size_t)NROWS * ND]; // bf16 X
__device__ __align__(256) float          g_dist[(size_t)NROWS * DSTR];

// ---------------------------------------------------------------- helpers
__device__ __forceinline__ uint32_t smem_u32(const void* p) {
    uint32_t a;
    asm("{ .reg .u64 t; cvta.to.shared.u64 t, %1; cvt.u32.u64 %0, t; }"
        : "=r"(a) : "l"(p));
    return a;
}
__device__ __forceinline__ void cp16(uint32_t dst, const void* src) {
    asm volatile("cp.async.cg.shared.global [%0], [%1], 16;"
                 :: "r"(dst), "l"(src) : "memory");
}
#define CP_COMMIT()  asm volatile("cp.async.commit_group;" ::: "memory")
#define CP_WAIT(n)   asm volatile("cp.async.wait_group %0;" :: "n"(n) : "memory")
#define SMEM_SWZ(o)  ((o) ^ (((o) >> 3) & 0x70))

__device__ __forceinline__ void mma_bf16(float* d, const uint32_t* a, const uint32_t* b) {
    asm volatile(
        "mma.sync.aligned.m16n8k16.row.col.f32.bf16.bf16.f32 "
        "{%0,%1,%2,%3}, {%4,%5,%6,%7}, {%8,%9}, {%0,%1,%2,%3};"
        : "+f"(d[0]), "+f"(d[1]), "+f"(d[2]), "+f"(d[3])
        : "r"(a[0]), "r"(a[1]), "r"(a[2]), "r"(a[3]), "r"(b[0]), "r"(b[1]));
}

// ---------------------------------------------------------------- kernel 0
// X (f32) -> g_Xb (bf16), 8 elems/thread, coalesced.
__global__ void convert_x_kernel(const float* __restrict__ X) {
    size_t i = ((size_t)blockIdx.x * 256 + threadIdx.x) * 8;
    float4 f0 = *(const float4*)(X + i);
    float4 f1 = *(const float4*)(X + i + 4);
    __nv_bfloat162 h0 = __floats2bfloat162_rn(f0.x, f0.y);
    __nv_bfloat162 h1 = __floats2bfloat162_rn(f0.z, f0.w);
    __nv_bfloat162 h2 = __floats2bfloat162_rn(f1.x, f1.y);
    __nv_bfloat162 h3 = __floats2bfloat162_rn(f1.z, f1.w);
    uint4 o;
    o.x = *(uint32_t*)&h0; o.y = *(uint32_t*)&h1;
    o.z = *(uint32_t*)&h2; o.w = *(uint32_t*)&h3;
    *(uint4*)(g_Xb + i) = o;
}

// ---------------------------------------------------------------- kernel 1
__global__ void transpose_C_kernel(const float* __restrict__ C) {
    int i = blockIdx.x * 256 + threadIdx.x;
    if (i >= NKP * ND) return;
    int k = i >> 10;
    int d = i & (ND - 1);
    float v = (k < NK) ? C[d * NK + k] : 0.0f;
    g_Ct[i]  = v;
    g_Ctb[i] = __float2bfloat16_rn(v);
}

// ---------------------------------------------------------------- kernel 2
// bf16 mma.sync GEMM, CTA 128(M) x 160(N), 8 warps (2m x 4n), warp 64x40.
// K chunks of 64 bf16 (one SW128 128B row), cp.async double-buffer, 2 CTAs/SM.
// (Exact R15 configuration — 595us proven.)
#define CH       16                     // 1024 / 64
#define A_BYTES  (128 * 128)            // 16 KB per buffer
#define B_BYTES  (160 * 128)            // 20 KB per buffer
#define BUF_BYTES (A_BYTES + B_BYTES)   // 36 KB
#define SMEM_TOT (2 * BUF_BYTES)        // 72 KB

__global__ __launch_bounds__(256, 2)
void dist_bf16_kernel(const float* __restrict__ Cn)
{
    extern __shared__ char smem[];
    const uint32_t sb = smem_u32(smem);

    const int tid  = threadIdx.x;
    const int warp = tid >> 5;
    const int lane = tid & 31;
    const int g    = lane >> 2;          // 0..7
    const int t    = lane & 3;           // 0..3
    const int m0   = (warp >> 2) * 64;   // 0 or 64
    const int n0w  = (warp & 3) * 40;    // 0,40,80,120

    const size_t row0 = (size_t)blockIdx.x * 128;
    const int    kc0  = blockIdx.y * 160;

    const __nv_bfloat16* xb = g_Xb  + row0 * ND;
    const __nv_bfloat16* cb = g_Ctb + (size_t)kc0 * ND;

    float acc[4][5][4];
    #pragma unroll
    for (int i = 0; i < 4; ++i)
        #pragma unroll
        for (int j = 0; j < 5; ++j)
            #pragma unroll
            for (int r = 0; r < 4; ++r) acc[i][j][r] = 0.0f;

    auto issue = [&](int c, int buf) {
        const int d0 = c * 64;                         // bf16 col base
        const uint32_t a_base = sb + buf * BUF_BYTES;
        const uint32_t b_base = a_base + A_BYTES;
        #pragma unroll
        for (int q = 0; q < 4; ++q) {                  // A: 1024 chunks / 256 thr
            int idx = tid + q * 256;
            int r = idx >> 3, bo = (idx & 7) * 16;     // bo: byte offset in row
            cp16(a_base + SMEM_SWZ((uint32_t)(r * 128 + bo)),
                 xb + (size_t)r * ND + d0 + (bo >> 1));
        }
        #pragma unroll
        for (int q = 0; q < 5; ++q) {                  // B: 1280 chunks / 256 thr
            int idx = tid + q * 256;
            int r = idx >> 3, bo = (idx & 7) * 16;
            cp16(b_base + SMEM_SWZ((uint32_t)(r * 128 + bo)),
                 cb + (size_t)r * ND + d0 + (bo >> 1));
        }
        CP_COMMIT();
    };

    issue(0, 0);
    issue(1, 1);

    for (int it = 0; it < CH; ++it) {
        const int cur = it & 1;
        if (it + 1 < CH) { CP_WAIT(1); } else { CP_WAIT(0); }   // tile it arrived
        __syncthreads();

        const char* As = smem + cur * BUF_BYTES;
        const char* Bs = As + A_BYTES;

        #pragma unroll
        for (int k16 = 0; k16 < 4; ++k16) {
            const int kb = k16 * 16;                    // bf16 col base in tile
            uint32_t af[4][4];
            #pragma unroll
            for (int i = 0; i < 4; ++i) {
                const int mr = m0 + 16 * i + g;
                af[i][0] = *(const uint32_t*)(As + SMEM_SWZ((uint32_t)(mr * 128 + (kb + 2*t) * 2)));
                af[i][1] = *(const uint32_t*)(As + SMEM_SWZ((uint32_t)((mr + 8) * 128 + (kb + 2*t) * 2)));
                af[i][2] = *(const uint32_t*)(As + SMEM_SWZ((uint32_t)(mr * 128 + (kb + 2*t + 8) * 2)));
                af[i][3] = *(const uint32_t*)(As + SMEM_SWZ((uint32_t)((mr + 8) * 128 + (kb + 2*t + 8) * 2)));
            }
            uint32_t bf[5][2];
            #pragma unroll
            for (int j = 0; j < 5; ++j) {
                const int nr = n0w + 8 * j + g;
                bf[j][0] = *(const uint32_t*)(Bs + SMEM_SWZ((uint32_t)(nr * 128 + (kb + 2*t) * 2)));
                bf[j][1] = *(const uint32_t*)(Bs + SMEM_SWZ((uint32_t)(nr * 128 + (kb + 2*t + 8) * 2)));
            }
            #pragma unroll
            for (int i = 0; i < 4; ++i)
                #pragma unroll
                for (int j = 0; j < 5; ++j)
                    mma_bf16(acc[i][j], af[i], bf[j]);
        }

        __syncthreads();                                // all warps done with cur buf
        if (it + 2 < CH) issue(it + 2, cur);            // refill cur buffer
    }

    // ---- epilogue: dist = Cn[k] - 2*dot (mapping verified R13/R15) ----
    #pragma unroll
    for (int j = 0; j < 5; ++j) {
        const int k0 = kc0 + n0w + 8 * j + 2 * t;
        const float cn0 = (k0     < NK) ? Cn[k0]     : 0.0f;
        const float cn1 = (k0 + 1 < NK) ? Cn[k0 + 1] : 0.0f;
        #pragma unroll
        for (int i = 0; i < 4; ++i) {
            const size_t r = row0 + m0 + 16 * i + g;
            if (k0 < NK) {
                g_dist[r * DSTR + k0]       = cn0 - 2.0f * acc[i][j][0];
                g_dist[(r + 8) * DSTR + k0] = cn0 - 2.0f * acc[i][j][2];
            }
            if (k0 + 1 < NK) {
                g_dist[r * DSTR + k0 + 1]       = cn1 - 2.0f * acc[i][j][1];
                g_dist[(r + 8) * DSTR + k0 + 1] = cn1 - 2.0f * acc[i][j][3];
            }
        }
    }
}

// ---------------------------------------------------------------- kernel 3
// Rescore v2: one warp per row, no smem. Approx min over 300, margin
// candidates, exact fp32 re-evaluation with float4 strided dots.
__global__ __launch_bounds__(256)
void rescore_kernel(const float* __restrict__ X,
                    const float* __restrict__ Cn,
                    float* __restrict__ out)
{
    const int tid  = threadIdx.x;
    const int warp = tid >> 5;
    const int lane = tid & 31;
    const size_t r = (size_t)blockIdx.x * 8 + warp;
    const float INF = __int_as_float(0x7f800000);
    const float MARGIN = 24.0f;          // bf16 chain bound ~12, 2x safety

    const float* drow = g_dist + r * DSTR;

    float vals[10];
    float minv = INF; int mink = 0;
    #pragma unroll
    for (int c = 0; c < 10; ++c) {
        int k = c * 32 + lane;
        float v = (k < NK) ? drow[k] : INF;
        vals[c] = v;
        if (v < minv) { minv = v; mink = k; }
    }
    #pragma unroll
    for (int off = 16; off; off >>= 1) {
        float ov = __shfl_xor_sync(0xffffffffu, minv, off);
        int   ok = __shfl_xor_sync(0xffffffffu, mink, off);
        if (ov < minv || (ov == minv && ok < mink)) { minv = ov; mink = ok; }
    }
    const float thr = minv + MARGIN;

    const float4* xr = (const float4*)(X + r * ND);

    float bestv = INF; int bestk = 0;
    #pragma unroll
    for (int c = 0; c < 10; ++c) {
        unsigned m = __ballot_sync(0xffffffffu, vals[c] < thr);
        while (m) {
            int b = __ffs(m) - 1; m &= m - 1;
            int k = c * 32 + b;                       // ascending k overall
            const float4* cr = (const float4*)(g_Ct + (size_t)k * ND);
            float s0 = 0.f, s1 = 0.f, s2 = 0.f, s3 = 0.f;
            #pragma unroll
            for (int i = 0; i < 8; ++i) {             // 256 float4 / 32 lanes
                float4 xv = __ldg(&xr[lane + i * 32]);
                float4 cv = __ldg(&cr[lane + i * 32]);
                s0 = fmaf(xv.x, cv.x, s0);
                s1 = fmaf(xv.y, cv.y, s1);
                s2 = fmaf(xv.z, cv.z, s2);
                s3 = fmaf(xv.w, cv.w, s3);
            }
            float a = (s0 + s1) + (s2 + s3);
            #pragma unroll
            for (int off = 16; off; off >>= 1)
                a += __shfl_xor_sync(0xffffffffu, a, off);
            float de = Cn[k] - 2.0f * a;              // exact fp32 distance
            if (de < bestv) { bestv = de; bestk = k; }  // strict <: first-min
        }
    }
    if (lane == 0) out[r] = (float)bestk;
}

// ---------------------------------------------------------------- launch
extern "C" void kernel_launch(void* const* d_in, const int* in_sizes, int n_in,
                              void* d_out, int out_size) {
    // Bind inputs BY ELEMENT COUNT (x = largest; C = 307200; Cnorm = 300).
    const float* x  = nullptr;
    const float* C  = nullptr;
    const float* Cn = nullptr;
    long long x_elems = 0;
    for (int i = 0; i < n_in; ++i) {
        const long long sz = in_sizes[i];
        if (sz > x_elems) { x = (const float*)d_in[i]; x_elems = sz; }
    }
    for (int i = 0; i < n_in; ++i) {
        const long long sz = in_sizes[i];
        if (sz == (long long)307200) C  = (const float*)d_in[i];
        else if (sz == (long long)300) Cn = (const float*)d_in[i];
    }
    if (!C || !Cn) {   // fallback, should not trigger
        x  = (const float*)d_in[0]; x_elems = in_sizes[0];
        C  = (const float*)d_in[1];
        Cn = (const float*)d_in[2];
    }

    float* out = (float*)d_out;                 // [131072] float32 token values
    const int n_rows = (int)(x_elems / ND);     // 131072

    convert_x_kernel<<<(unsigned)(x_elems / (256 * 8)), 256>>>(x);
    transpose_C_kernel<<<(NKP * ND + 255) / 256, 256>>>(C);

    cudaFuncSetAttribute(dist_bf16_kernel,
                         cudaFuncAttributeMaxDynamicSharedMemorySize, SMEM_TOT);
    dim3 gridB(n_rows / 128, NKP / 160);        // (1024, 2)
    dist_bf16_kernel<<<gridB, 256, SMEM_TOT>>>(Cn);

    rescore_kernel<<<n_rows / 8, 256>>>(x, Cn, out);
}